// round 1
// baseline (speedup 1.0000x reference)
#include <cuda_runtime.h>
#include <cuda_fp16.h>
#include <cstdint>

#define N_NEURON 4096
#define N_BATCH  32
#define N_STEPS  300

// ---------------- device scratch (allocation-free rule: __device__ globals) ----
__device__ __align__(256) __half g_W16[(size_t)N_NEURON * N_NEURON];     // 32 MB fp16 W
__device__ __align__(256) __half g_r16[2][N_BATCH * N_NEURON];           // ping-pong GEMM input
__device__ float g_rates[N_BATCH * N_NEURON];
__device__ float g_rec[N_BATCH * N_NEURON];
__device__ float g_acc[N_BATCH * N_NEURON];

// ---------------- W fp32 -> fp16 (runs once per replay) ----------------------
__global__ void convert_w(const float* __restrict__ W) {
    int i = blockIdx.x * blockDim.x + threadIdx.x;
    int stride = gridDim.x * blockDim.x;
    const float2* W2 = (const float2*)W;
    __half2* out = (__half2*)g_W16;
    const int n2 = (int)((size_t)N_NEURON * N_NEURON / 2);
    for (; i < n2; i += stride) {
        float2 v = W2[i];
        out[i] = __floats2half2_rn(v.x, v.y);
    }
}

// ---------------- state init: rates0 = relu(ff[:,0] + rec0) ------------------
__global__ void init_state(const float* __restrict__ ff, const float* __restrict__ rec0) {
    int i = blockIdx.x * blockDim.x + threadIdx.x;
    if (i >= N_BATCH * N_NEURON) return;
    int b = i >> 12;           // /4096
    int j = i & (N_NEURON - 1);
    float r0 = rec0[i];
    float f  = ff[(size_t)b * N_STEPS * N_NEURON + j];   // ff[b, 0, j]
    float rate = fmaxf(f + r0, 0.0f);
    g_rates[i] = rate;
    g_rec[i]   = r0;
    g_acc[i]   = 0.0f;
    g_r16[0][i] = __float2half(rate);
}

// ---------------- fused step: GEMM (HMMA) + dynamics + window accum ----------
#define KC  64      // K elements per smem chunk
#define LDA 72      // padded A row (halves): conflict-free ldmatrix
#define LDB 40      // padded B row (halves): conflict-free ldmatrix

__device__ __forceinline__ uint32_t smem_u32(const void* p) {
    return (uint32_t)__cvta_generic_to_shared(p);
}

__device__ __forceinline__ void load_chunk(
    __half (*As)[32][LDA], __half (*Bs)[KC][LDB],
    const __half* __restrict__ A_g, const __half* __restrict__ B_g,
    int tid, int j0, int k0, int buf)
{
    // A: 32 rows x 64 halves = 256 segments of 16B (2 per thread)
    #pragma unroll
    for (int s = tid; s < 256; s += 128) {
        int row = s >> 3, seg = s & 7;
        uint32_t dst = smem_u32(&As[buf][row][seg * 8]);
        const __half* src = A_g + (size_t)row * N_NEURON + k0 + seg * 8;
        asm volatile("cp.async.cg.shared.global [%0], [%1], 16;\n" :: "r"(dst), "l"(src));
    }
    // B (W tile): 64 k-rows x 32 halves = 256 segments of 16B
    #pragma unroll
    for (int s = tid; s < 256; s += 128) {
        int row = s >> 2, seg = s & 3;
        uint32_t dst = smem_u32(&Bs[buf][row][seg * 8]);
        const __half* src = B_g + (size_t)(k0 + row) * N_NEURON + j0 + seg * 8;
        asm volatile("cp.async.cg.shared.global [%0], [%1], 16;\n" :: "r"(dst), "l"(src));
    }
}

__global__ void __launch_bounds__(128, 1) step_kernel(
    const float* __restrict__ ff, float* __restrict__ out, int t)
{
    __shared__ __align__(16) __half As[2][32][LDA];
    __shared__ __align__(16) __half Bs[2][KC][LDB];

    const int tid  = threadIdx.x;
    const int warp = tid >> 5;
    const int lane = tid & 31;
    const int j0   = blockIdx.x * 32;
    const int cur  = t & 1, nxt = cur ^ 1;
    const __half* A_g = g_r16[cur];
    const __half* B_g = g_W16;

    float c[2][4] = {{0.f,0.f,0.f,0.f},{0.f,0.f,0.f,0.f}};

    load_chunk(As, Bs, A_g, B_g, tid, j0, 0, 0);
    asm volatile("cp.async.commit_group;\n");

    const int NCHUNK = N_NEURON / KC;   // 64
    for (int ch = 0; ch < NCHUNK; ++ch) {
        int buf = ch & 1;
        if (ch + 1 < NCHUNK)
            load_chunk(As, Bs, A_g, B_g, tid, j0, (ch + 1) * KC, buf ^ 1);
        asm volatile("cp.async.commit_group;\n");
        asm volatile("cp.async.wait_group 1;\n");
        __syncthreads();

        const int r   = lane & 15;
        const int sel = lane >> 4;
        #pragma unroll
        for (int ks = 0; ks < KC; ks += 16) {
            uint32_t a[2][4], b0, b1;
            #pragma unroll
            for (int rb = 0; rb < 2; ++rb) {
                uint32_t addr = smem_u32(&As[buf][rb * 16 + r][ks + sel * 8]);
                asm volatile("ldmatrix.sync.aligned.m8n8.x4.shared.b16 {%0,%1,%2,%3}, [%4];\n"
                    : "=r"(a[rb][0]), "=r"(a[rb][1]), "=r"(a[rb][2]), "=r"(a[rb][3])
                    : "r"(addr));
            }
            {
                uint32_t addr = smem_u32(&Bs[buf][ks + r][warp * 8]);
                asm volatile("ldmatrix.sync.aligned.m8n8.x2.trans.shared.b16 {%0,%1}, [%2];\n"
                    : "=r"(b0), "=r"(b1) : "r"(addr));
            }
            #pragma unroll
            for (int rb = 0; rb < 2; ++rb) {
                asm volatile("mma.sync.aligned.m16n8k16.row.col.f32.f16.f16.f32 "
                    "{%0,%1,%2,%3}, {%4,%5,%6,%7}, {%8,%9}, {%0,%1,%2,%3};\n"
                    : "+f"(c[rb][0]), "+f"(c[rb][1]), "+f"(c[rb][2]), "+f"(c[rb][3])
                    : "r"(a[rb][0]), "r"(a[rb][1]), "r"(a[rb][2]), "r"(a[rb][3]),
                      "r"(b0), "r"(b1));
            }
        }
        __syncthreads();
    }

    // ---- fused dynamics + window accumulation (each thread owns 8 (b,j)) ----
    const float E_SYN  = 0.95122942450071403f;  // exp(-dt/tau_syn), dt/tau_syn=0.05
    const float DT_SYN = 0.05f;
    const float E_TAU  = 0.90483741803595957f;  // exp(-dt/tau), dt/tau=0.1
    const float DT_TAU = 0.1f;

    const bool do_acc = (t >= 90);
    const bool do_rec = (t >= 100) && (((t - 100) % 10) == 0);
    const int  w      = (t - 100) / 10;

    #pragma unroll
    for (int rb = 0; rb < 2; ++rb) {
        #pragma unroll
        for (int i = 0; i < 4; ++i) {
            int bb  = rb * 16 + (lane >> 2) + ((i >= 2) ? 8 : 0);
            int j   = j0 + warp * 8 + (lane & 3) * 2 + (i & 1);
            int idx = bb * N_NEURON + j;
            float hidden = c[rb][i];
            float rec  = g_rec[idx] * E_SYN + hidden * DT_SYN;
            float f    = ff[((size_t)bb * N_STEPS + t) * N_NEURON + j];
            float nl   = fmaxf(f + rec, 0.0f);
            float rate = g_rates[idx] * E_TAU + nl * DT_TAU;
            g_rec[idx]   = rec;
            g_rates[idx] = rate;
            g_r16[nxt][idx] = __float2half(rate);
            if (do_acc) {
                float a = g_acc[idx] + rate;
                if (do_rec) {
                    out[((size_t)bb * 20 + w) * N_NEURON + j] = a * 0.1f;
                    a = 0.0f;
                }
                g_acc[idx] = a;
            }
        }
    }
}

// ---------------- launch ------------------------------------------------------
extern "C" void kernel_launch(void* const* d_in, const int* in_sizes, int n_in,
                              void* d_out, int out_size) {
    const float* W    = (const float*)d_in[0];   // Wab_T [4096,4096] f32
    const float* ff   = (const float*)d_in[1];   // ff_input [32,300,4096] f32
    const float* rec0 = (const float*)d_in[2];   // rec0 [32,4096] f32
    float* out = (float*)d_out;                  // [32,20,4096] f32

    convert_w<<<2048, 256>>>(W);
    init_state<<<(N_BATCH * N_NEURON + 255) / 256, 256>>>(ff, rec0);
    for (int t = 0; t < N_STEPS; ++t)
        step_kernel<<<N_NEURON / 32, 128>>>(ff, out, t);
}

// round 2
// speedup vs baseline: 2.3746x; 2.3746x over previous
#include <cuda_runtime.h>
#include <cuda_fp16.h>
#include <cstdint>

#define N_NEURON 4096
#define N_BATCH  32
#define N_STEPS  300

// ---------------- device scratch (allocation-free rule: __device__ globals) ----
// W reordered per 32-col tile, contiguous: g_W16[tile][k][32]
__device__ __align__(256) __half g_W16[(size_t)N_NEURON * N_NEURON];
__device__ __align__(256) __half g_r16[2][N_BATCH * N_NEURON];   // rates fp16, [b][j], ping-pong
__device__ float g_rates[N_BATCH * N_NEURON];
__device__ float g_rec[N_BATCH * N_NEURON];
__device__ float g_acc[N_BATCH * N_NEURON];

// ---------------- W fp32 -> fp16 + tile reorder (once per replay) -------------
__global__ void convert_w(const float* __restrict__ W) {
    int i = blockIdx.x * blockDim.x + threadIdx.x;
    int stride = gridDim.x * blockDim.x;
    const int n2 = (int)((size_t)N_NEURON * N_NEURON / 2);   // half2 pairs
    const float2* W2 = (const float2*)W;
    __half2* out = (__half2*)g_W16;
    for (; i < n2; i += stride) {
        int k  = i >> 11;            // row (4096/2 = 2048 pairs per row)
        int jp = i & 2047;
        int j  = jp * 2;
        int tile = j >> 5;
        int c    = j & 31;
        float2 v = W2[i];
        size_t o = ((size_t)tile * N_NEURON * 32 + (size_t)k * 32 + c) >> 1;
        out[o] = __floats2half2_rn(v.x, v.y);
    }
}

// ---------------- state init: rates0 = relu(ff[:,0] + rec0) ------------------
__global__ void init_state(const float* __restrict__ ff, const float* __restrict__ rec0) {
    int i = blockIdx.x * blockDim.x + threadIdx.x;
    if (i >= N_BATCH * N_NEURON) return;
    int b = i >> 12;
    int j = i & (N_NEURON - 1);
    float r0 = rec0[i];
    float f  = ff[(size_t)b * N_STEPS * N_NEURON + j];   // ff[b, 0, j]
    float rate = fmaxf(f + r0, 0.0f);
    g_rates[i] = rate;
    g_rec[i]   = r0;
    g_acc[i]   = 0.0f;
    g_r16[0][i] = __float2half(rate);
}

// ---------------- fused step ---------------------------------------------------
#define KC      128                 // K per pipeline stage
#define NSTAGE  4
#define LDA     (KC + 8)            // padded A row (halves)
#define LDB     40                  // padded B row (halves)
#define SA_H    (32 * LDA)          // halves per A stage
#define SB_H    (KC * LDB)          // halves per B stage
#define SMEM_A_BYTES   (NSTAGE * SA_H * 2)
#define SMEM_B_BYTES   (NSTAGE * SB_H * 2)
#define SMEM_RED_BYTES (8 * 32 * 32 * 4)
#define SMEM_TOTAL     (SMEM_A_BYTES + SMEM_B_BYTES + SMEM_RED_BYTES)

__device__ __forceinline__ uint32_t smem_u32(const void* p) {
    return (uint32_t)__cvta_generic_to_shared(p);
}

__device__ __forceinline__ void load_stage(
    __half* As, __half* Bs,
    const __half* __restrict__ A_g, const __half* __restrict__ B_t,
    int tid, int k0, int st)
{
    __half* Ad = As + st * SA_H;
    __half* Bd = Bs + st * SB_H;
    // A: 32 rows x KC halves = 512 segs of 16B; 256 threads -> 2 each
    #pragma unroll
    for (int s = tid; s < 32 * (KC / 8); s += 256) {
        int row = s >> 4, seg = s & 15;
        uint32_t dst = smem_u32(Ad + row * LDA + seg * 8);
        const __half* src = A_g + (size_t)row * N_NEURON + k0 + seg * 8;
        asm volatile("cp.async.cg.shared.global [%0], [%1], 16;\n" :: "r"(dst), "l"(src));
    }
    // B: KC rows x 32 halves = 512 segs of 16B, contiguous source
    #pragma unroll
    for (int s = tid; s < KC * 4; s += 256) {
        int row = s >> 2, seg = s & 3;
        uint32_t dst = smem_u32(Bd + row * LDB + seg * 8);
        const __half* src = B_t + (size_t)k0 * 32 + s * 8;
        asm volatile("cp.async.cg.shared.global [%0], [%1], 16;\n" :: "r"(dst), "l"(src));
    }
}

__global__ void __launch_bounds__(256, 1) step_kernel(
    const float* __restrict__ ff, float* __restrict__ out, int t)
{
    extern __shared__ __align__(16) char sm[];
    __half* As = (__half*)sm;
    __half* Bs = (__half*)(sm + SMEM_A_BYTES);
    float*  red = (float*)(sm + SMEM_A_BYTES + SMEM_B_BYTES);

    const int tid  = threadIdx.x;
    const int warp = tid >> 5;          // 0..7, owns k-rows [warp*16, warp*16+16) per stage
    const int lane = tid & 31;
    const int j0   = blockIdx.x * 32;
    const int cur  = t & 1, nxt = cur ^ 1;
    const __half* A_g = g_r16[cur];
    const __half* B_t = g_W16 + (size_t)blockIdx.x * N_NEURON * 32;

    float c[2][4][4];
    #pragma unroll
    for (int rb = 0; rb < 2; ++rb)
        #pragma unroll
        for (int nb = 0; nb < 4; ++nb)
            #pragma unroll
            for (int i = 0; i < 4; ++i) c[rb][nb][i] = 0.f;

    const int NCHUNK = N_NEURON / KC;   // 32

    // prologue: 3 stages in flight
    #pragma unroll
    for (int p = 0; p < 3; ++p) {
        load_stage(As, Bs, A_g, B_t, tid, p * KC, p);
        asm volatile("cp.async.commit_group;\n");
    }

    const int r   = lane & 15;
    const int sel = lane >> 4;
    const int kw  = warp * 16;

    for (int ch = 0; ch < NCHUNK; ++ch) {
        asm volatile("cp.async.wait_group 2;\n");
        __syncthreads();
        if (ch + 3 < NCHUNK)
            load_stage(As, Bs, A_g, B_t, tid, (ch + 3) * KC, (ch + 3) & (NSTAGE - 1));
        asm volatile("cp.async.commit_group;\n");

        const int st = ch & (NSTAGE - 1);
        __half* Ast = As + st * SA_H;
        __half* Bst = Bs + st * SB_H;

        uint32_t a[2][4], b[4][2];
        #pragma unroll
        for (int rb = 0; rb < 2; ++rb) {
            uint32_t addr = smem_u32(Ast + (rb * 16 + r) * LDA + kw + sel * 8);
            asm volatile("ldmatrix.sync.aligned.m8n8.x4.shared.b16 {%0,%1,%2,%3}, [%4];\n"
                : "=r"(a[rb][0]), "=r"(a[rb][1]), "=r"(a[rb][2]), "=r"(a[rb][3])
                : "r"(addr));
        }
        #pragma unroll
        for (int nb = 0; nb < 4; ++nb) {
            uint32_t addr = smem_u32(Bst + (kw + r) * LDB + nb * 8);
            asm volatile("ldmatrix.sync.aligned.m8n8.x2.trans.shared.b16 {%0,%1}, [%2];\n"
                : "=r"(b[nb][0]), "=r"(b[nb][1]) : "r"(addr));
        }
        #pragma unroll
        for (int rb = 0; rb < 2; ++rb)
            #pragma unroll
            for (int nb = 0; nb < 4; ++nb) {
                asm volatile("mma.sync.aligned.m16n8k16.row.col.f32.f16.f16.f32 "
                    "{%0,%1,%2,%3}, {%4,%5,%6,%7}, {%8,%9}, {%0,%1,%2,%3};\n"
                    : "+f"(c[rb][nb][0]), "+f"(c[rb][nb][1]),
                      "+f"(c[rb][nb][2]), "+f"(c[rb][nb][3])
                    : "r"(a[rb][0]), "r"(a[rb][1]), "r"(a[rb][2]), "r"(a[rb][3]),
                      "r"(b[nb][0]), "r"(b[nb][1]));
            }
    }

    // ---- cross-warp k-reduction through smem ----
    float* myred = red + warp * 1024;
    #pragma unroll
    for (int rb = 0; rb < 2; ++rb)
        #pragma unroll
        for (int nb = 0; nb < 4; ++nb)
            #pragma unroll
            for (int i = 0; i < 4; ++i) {
                int m = rb * 16 + (lane >> 2) + ((i >= 2) ? 8 : 0);
                int n = nb * 8 + (lane & 3) * 2 + (i & 1);
                myred[m * 32 + n] = c[rb][nb][i];
            }
    __syncthreads();

    // ---- fused dynamics + window accumulation: thread owns (b, 4 consecutive j)
    const float E_SYN  = 0.95122942450071403f;  // exp(-dt/tau_syn)
    const float DT_SYN = 0.05f;
    const float E_TAU  = 0.90483741803595957f;  // exp(-dt/tau)
    const float DT_TAU = 0.1f;

    const bool do_acc = (t >= 90);
    const bool do_rec = (t >= 100) && (((t - 100) % 10) == 0);
    const int  w      = (t - 100) / 10;

    const int bb = tid >> 3;
    const int jl = (tid & 7) * 4;
    const int j  = j0 + jl;
    const size_t idx = (size_t)bb * N_NEURON + j;

    float h[4] = {0.f, 0.f, 0.f, 0.f};
    #pragma unroll
    for (int ww = 0; ww < 8; ++ww) {
        float4 p = *(const float4*)&red[ww * 1024 + bb * 32 + jl];
        h[0] += p.x; h[1] += p.y; h[2] += p.z; h[3] += p.w;
    }

    float4 rec4  = *(const float4*)&g_rec[idx];
    float4 rate4 = *(const float4*)&g_rates[idx];
    float4 ff4   = *(const float4*)&ff[((size_t)bb * N_STEPS + t) * N_NEURON + j];

    float rc[4] = {rec4.x, rec4.y, rec4.z, rec4.w};
    float rt[4] = {rate4.x, rate4.y, rate4.z, rate4.w};
    float fv[4] = {ff4.x, ff4.y, ff4.z, ff4.w};
    #pragma unroll
    for (int x = 0; x < 4; ++x) {
        rc[x] = rc[x] * E_SYN + h[x] * DT_SYN;
        float nl = fmaxf(fv[x] + rc[x], 0.0f);
        rt[x] = rt[x] * E_TAU + nl * DT_TAU;
    }
    *(float4*)&g_rec[idx]   = make_float4(rc[0], rc[1], rc[2], rc[3]);
    *(float4*)&g_rates[idx] = make_float4(rt[0], rt[1], rt[2], rt[3]);
    __half2* r16o = (__half2*)&g_r16[nxt][idx];
    r16o[0] = __floats2half2_rn(rt[0], rt[1]);
    r16o[1] = __floats2half2_rn(rt[2], rt[3]);

    if (do_acc) {
        float4 a4 = *(const float4*)&g_acc[idx];
        float av[4] = {a4.x + rt[0], a4.y + rt[1], a4.z + rt[2], a4.w + rt[3]};
        if (do_rec) {
            *(float4*)&out[((size_t)bb * 20 + w) * N_NEURON + j] =
                make_float4(av[0] * 0.1f, av[1] * 0.1f, av[2] * 0.1f, av[3] * 0.1f);
            av[0] = av[1] = av[2] = av[3] = 0.f;
        }
        *(float4*)&g_acc[idx] = make_float4(av[0], av[1], av[2], av[3]);
    }
}

// ---------------- launch ------------------------------------------------------
extern "C" void kernel_launch(void* const* d_in, const int* in_sizes, int n_in,
                              void* d_out, int out_size) {
    const float* W    = (const float*)d_in[0];   // Wab_T [4096,4096] f32
    const float* ff   = (const float*)d_in[1];   // ff_input [32,300,4096] f32
    const float* rec0 = (const float*)d_in[2];   // rec0 [32,4096] f32
    float* out = (float*)d_out;                  // [32,20,4096] f32

    cudaFuncSetAttribute(step_kernel, cudaFuncAttributeMaxDynamicSharedMemorySize, SMEM_TOTAL);

    convert_w<<<2048, 256>>>(W);
    init_state<<<(N_BATCH * N_NEURON + 255) / 256, 256>>>(ff, rec0);
    for (int t = 0; t < N_STEPS; ++t)
        step_kernel<<<N_NEURON / 32, 256, SMEM_TOTAL>>>(ff, out, t);
}

// round 3
// speedup vs baseline: 4.1864x; 1.7630x over previous
#include <cuda_runtime.h>
#include <cuda_fp16.h>
#include <cstdint>

#define N_NEURON 4096
#define N_BATCH  32
#define N_STEPS  300

// ---------------- device scratch (allocation-free rule: __device__ globals) ----
// W packed in per-lane MMA B-fragment layout:
//   entry (jt, kb, lane) = 16 halves (32 B):
//   halves[nb*4 + {0,1,2,3}] = W[k][j] for k = kb*16+(lane&3)*2 + {0,1,8,9},
//                                          j = jt*32 + nb*8 + (lane>>2)
__device__ __align__(256) __half g_W16[(size_t)N_NEURON * N_NEURON];
// rates in per-lane MMA A-fragment layout (ping-pong):
//   entry (kb, rb, lane) = 8 halves (16 B) = a0,a1,a2,a3:
//   a0 = rates[rb*16+g][k0..k0+1], a1 = +8 row, a2 = +8 k, a3 = both
//   g = lane>>2, k0 = kb*16+(lane&3)*2
__device__ __align__(256) __half g_r16[2][N_BATCH * N_NEURON];
__device__ float g_rates[N_BATCH * N_NEURON];
__device__ float g_rec[N_BATCH * N_NEURON];
__device__ float g_acc[N_BATCH * N_NEURON];

// ---------------- W fp32 -> fp16 fragment pack (once per replay) --------------
__global__ void convert_w(const float* __restrict__ W) {
    // one thread per (jt, kb, lane) entry: 128*256*32 = 1,048,576
    int idx = blockIdx.x * blockDim.x + threadIdx.x;
    if (idx >= 128 * 256 * 32) return;
    int lane = idx & 31;
    int kb   = (idx >> 5) & 255;
    int jt   = idx >> 13;
    int k0   = kb * 16 + (lane & 3) * 2;
    int g    = lane >> 2;
    __half h[16];
    #pragma unroll
    for (int nb = 0; nb < 4; ++nb) {
        int j = jt * 32 + nb * 8 + g;
        h[nb * 4 + 0] = __float2half(W[(size_t)(k0    ) * N_NEURON + j]);
        h[nb * 4 + 1] = __float2half(W[(size_t)(k0 + 1) * N_NEURON + j]);
        h[nb * 4 + 2] = __float2half(W[(size_t)(k0 + 8) * N_NEURON + j]);
        h[nb * 4 + 3] = __float2half(W[(size_t)(k0 + 9) * N_NEURON + j]);
    }
    uint4* dst = (uint4*)(g_W16 + (size_t)idx * 16);
    dst[0] = ((const uint4*)h)[0];
    dst[1] = ((const uint4*)h)[1];
}

// ---------------- state init: rates0 = relu(ff[:,0] + rec0) ------------------
__global__ void init_state(const float* __restrict__ ff, const float* __restrict__ rec0) {
    int i = blockIdx.x * blockDim.x + threadIdx.x;
    if (i >= N_BATCH * N_NEURON) return;
    int b = i >> 12;
    int j = i & (N_NEURON - 1);
    float r0 = rec0[i];
    float f  = ff[(size_t)b * N_STEPS * N_NEURON + j];   // ff[b, 0, j]
    float rate = fmaxf(f + r0, 0.0f);
    g_rates[i] = rate;
    g_rec[i]   = r0;
    g_acc[i]   = 0.0f;
    // A-fragment position
    int kb = j >> 4, kk = j & 15, rb = b >> 4, g = b & 7;
    int reg  = ((b >> 3) & 1) | ((kk >> 3) << 1);
    int lane = (g << 2) | ((kk & 7) >> 1);
    g_r16[0][(((size_t)(kb * 2 + rb) * 32 + lane) << 3) + (reg << 1) + (kk & 1)] =
        __float2half(rate);
}

// ---------------- fused step: all-LDG fragment GEMM + dynamics ----------------
__device__ __forceinline__ void mma_16816(float c[4], const uint4& a, uint32_t b0, uint32_t b1) {
    asm volatile("mma.sync.aligned.m16n8k16.row.col.f32.f16.f16.f32 "
        "{%0,%1,%2,%3}, {%4,%5,%6,%7}, {%8,%9}, {%0,%1,%2,%3};\n"
        : "+f"(c[0]), "+f"(c[1]), "+f"(c[2]), "+f"(c[3])
        : "r"(a.x), "r"(a.y), "r"(a.z), "r"(a.w), "r"(b0), "r"(b1));
}

__global__ void __launch_bounds__(256, 1) step_kernel(
    const float* __restrict__ ff, float* __restrict__ out, int t)
{
    __shared__ float red[8][N_BATCH * 32];

    const int tid  = threadIdx.x;
    const int warp = tid >> 5;          // 0..7: k-slice [warp*512, warp*512+512)
    const int lane = tid & 31;
    const int jt   = blockIdx.x;
    const int j0   = jt * 32;
    const int cur  = t & 1, nxt = cur ^ 1;

    const uint4* __restrict__ gA = (const uint4*)g_r16[cur];
    const uint4* __restrict__ gB = (const uint4*)g_W16 + ((size_t)jt * 256 + 0) * 64;
    // gB entry for (kb, lane): 2 uint4 at gB[(kb*32+lane)*2]

    // prefetch ff for epilogue
    const int bb = tid >> 3;
    const int jl = (tid & 7) * 4;
    const int j  = j0 + jl;
    const float4 ffv = *(const float4*)&ff[((size_t)bb * N_STEPS + t) * N_NEURON + j];

    float c[2][4][4];
    #pragma unroll
    for (int rb = 0; rb < 2; ++rb)
        #pragma unroll
        for (int nb = 0; nb < 4; ++nb)
            #pragma unroll
            for (int i = 0; i < 4; ++i) c[rb][nb][i] = 0.f;

    const int kb0 = warp * 32;          // 32 k-blocks of 16 per warp

    uint4 A0[4], A1[4], B0[4], B1[4];
    #pragma unroll
    for (int p = 0; p < 4; ++p) {
        int kb = kb0 + p;
        A0[p] = __ldg(&gA[(kb * 2 + 0) * 32 + lane]);
        A1[p] = __ldg(&gA[(kb * 2 + 1) * 32 + lane]);
        B0[p] = __ldg(&gB[(kb * 32 + lane) * 2 + 0]);
        B1[p] = __ldg(&gB[(kb * 32 + lane) * 2 + 1]);
    }

    #pragma unroll
    for (int i = 0; i < 32; ++i) {
        const int s = i & 3;
        // compute with slot s (loaded 4 iterations ago)
        mma_16816(c[0][0], A0[s], B0[s].x, B0[s].y);
        mma_16816(c[0][1], A0[s], B0[s].z, B0[s].w);
        mma_16816(c[0][2], A0[s], B1[s].x, B1[s].y);
        mma_16816(c[0][3], A0[s], B1[s].z, B1[s].w);
        mma_16816(c[1][0], A1[s], B0[s].x, B0[s].y);
        mma_16816(c[1][1], A1[s], B0[s].z, B0[s].w);
        mma_16816(c[1][2], A1[s], B1[s].x, B1[s].y);
        mma_16816(c[1][3], A1[s], B1[s].z, B1[s].w);
        if (i + 4 < 32) {
            int kb = kb0 + i + 4;
            A0[s] = __ldg(&gA[(kb * 2 + 0) * 32 + lane]);
            A1[s] = __ldg(&gA[(kb * 2 + 1) * 32 + lane]);
            B0[s] = __ldg(&gB[(kb * 32 + lane) * 2 + 0]);
            B1[s] = __ldg(&gB[(kb * 32 + lane) * 2 + 1]);
        }
    }

    // ---- cross-warp k-reduction through smem (single barrier) ----
    float* myred = red[warp];
    #pragma unroll
    for (int rb = 0; rb < 2; ++rb)
        #pragma unroll
        for (int nb = 0; nb < 4; ++nb)
            #pragma unroll
            for (int i = 0; i < 4; ++i) {
                int m = rb * 16 + (lane >> 2) + ((i >= 2) ? 8 : 0);
                int n = nb * 8 + (lane & 3) * 2 + (i & 1);
                myred[m * 32 + n] = c[rb][nb][i];
            }
    __syncthreads();

    // ---- fused dynamics + window accumulation: thread owns (bb, j..j+3) -----
    const float E_SYN  = 0.95122942450071403f;  // exp(-dt/tau_syn)
    const float DT_SYN = 0.05f;
    const float E_TAU  = 0.90483741803595957f;  // exp(-dt/tau)
    const float DT_TAU = 0.1f;

    const bool do_acc = (t >= 90);
    const bool do_rec = (t >= 100) && (((t - 100) % 10) == 0);
    const int  w      = (t - 100) / 10;

    const size_t idx = (size_t)bb * N_NEURON + j;

    float h[4] = {0.f, 0.f, 0.f, 0.f};
    #pragma unroll
    for (int ww = 0; ww < 8; ++ww) {
        float4 p = *(const float4*)&red[ww][bb * 32 + jl];
        h[0] += p.x; h[1] += p.y; h[2] += p.z; h[3] += p.w;
    }

    float4 rec4  = *(const float4*)&g_rec[idx];
    float4 rate4 = *(const float4*)&g_rates[idx];

    float rc[4] = {rec4.x, rec4.y, rec4.z, rec4.w};
    float rt[4] = {rate4.x, rate4.y, rate4.z, rate4.w};
    float fv[4] = {ffv.x, ffv.y, ffv.z, ffv.w};
    #pragma unroll
    for (int x = 0; x < 4; ++x) {
        rc[x] = rc[x] * E_SYN + h[x] * DT_SYN;
        float nl = fmaxf(fv[x] + rc[x], 0.0f);
        rt[x] = rt[x] * E_TAU + nl * DT_TAU;
    }
    *(float4*)&g_rec[idx]   = make_float4(rc[0], rc[1], rc[2], rc[3]);
    *(float4*)&g_rates[idx] = make_float4(rt[0], rt[1], rt[2], rt[3]);

    // next-step rates in A-fragment layout: two half2 stores
    {
        int kb = j >> 4, kk = j & 15;       // kk in {0,4,8,12}
        int rb = bb >> 4, g = bb & 7;
        int reg   = ((bb >> 3) & 1) | ((kk >> 3) << 1);
        int lane0 = (g << 2) | ((kk & 7) >> 1);
        __half2* base = (__half2*)g_r16[nxt];
        base[((size_t)(kb * 2 + rb) * 32 + lane0    ) * 4 + reg] = __floats2half2_rn(rt[0], rt[1]);
        base[((size_t)(kb * 2 + rb) * 32 + lane0 + 1) * 4 + reg] = __floats2half2_rn(rt[2], rt[3]);
    }

    if (do_acc) {
        float4 a4 = *(const float4*)&g_acc[idx];
        float av[4] = {a4.x + rt[0], a4.y + rt[1], a4.z + rt[2], a4.w + rt[3]};
        if (do_rec) {
            *(float4*)&out[((size_t)bb * 20 + w) * N_NEURON + j] =
                make_float4(av[0] * 0.1f, av[1] * 0.1f, av[2] * 0.1f, av[3] * 0.1f);
            av[0] = av[1] = av[2] = av[3] = 0.f;
        }
        *(float4*)&g_acc[idx] = make_float4(av[0], av[1], av[2], av[3]);
    }
}

// ---------------- launch ------------------------------------------------------
extern "C" void kernel_launch(void* const* d_in, const int* in_sizes, int n_in,
                              void* d_out, int out_size) {
    const float* W    = (const float*)d_in[0];   // Wab_T [4096,4096] f32
    const float* ff   = (const float*)d_in[1];   // ff_input [32,300,4096] f32
    const float* rec0 = (const float*)d_in[2];   // rec0 [32,4096] f32
    float* out = (float*)d_out;                  // [32,20,4096] f32

    convert_w<<<(128 * 256 * 32 + 255) / 256, 256>>>(W);
    init_state<<<(N_BATCH * N_NEURON + 255) / 256, 256>>>(ff, rec0);
    for (int t = 0; t < N_STEPS; ++t)
        step_kernel<<<N_NEURON / 32, 256>>>(ff, out, t);
}